// round 1
// baseline (speedup 1.0000x reference)
#include <cuda_runtime.h>
#include <math.h>

// Problem constants
// b=2, t=8, L=1024, c=256, H=8, D=32
#define M_ROWS 16384           // b*t*L
#define CDIM   256
#define NHEAD  8
#define DHEAD  32
#define LSEQ   1024
#define BTH    128             // b*t*H

// Scratch (device globals; no allocation allowed)
__device__ float g_qn[4194304];   // [bt, h, l, d]
__device__ float g_kn[4194304];
__device__ float g_vn[4194304];
__device__ float g_att[4194304];  // [bt, l, c]

// ---------------------------------------------------------------------------
// Kernel 1: Y = X @ W^T + bias, split heads, L2-normalize over d, write
// to [bt, h, l, d] layout.  Tile: 128(M) x 64(N), BK=16, 256 threads,
// 8x4 micro-tile per thread.
// ---------------------------------------------------------------------------
__global__ __launch_bounds__(256) void proj_norm_kernel(
    const float* __restrict__ X, const float* __restrict__ W,
    const float* __restrict__ bias, int sel)
{
    __shared__ float Asm[16][128];
    __shared__ float Wsm[16][64];
    __shared__ float Cs[128][65];
    __shared__ float scl[128][2];

    float* Out = (sel == 0) ? g_qn : (sel == 1) ? g_kn : g_vn;

    const int tid = threadIdx.x;
    const int tx = tid & 15, ty = tid >> 4;
    const int rowBase = blockIdx.x * 128;
    const int colBase = blockIdx.y * 64;

    float acc[8][4];
#pragma unroll
    for (int i = 0; i < 8; i++)
#pragma unroll
        for (int j = 0; j < 4; j++) acc[i][j] = 0.f;

    for (int kt = 0; kt < 16; ++kt) {
        // Load A tile 128x16 (transposed into smem)
#pragma unroll
        for (int rep = 0; rep < 2; ++rep) {
            int f = tid + rep * 256;
            int r = f >> 2, c4 = f & 3;
            float4 v = *(const float4*)(X + (size_t)(rowBase + r) * CDIM + kt * 16 + c4 * 4);
            Asm[c4 * 4 + 0][r] = v.x;
            Asm[c4 * 4 + 1][r] = v.y;
            Asm[c4 * 4 + 2][r] = v.z;
            Asm[c4 * 4 + 3][r] = v.w;
        }
        // Load W tile 64x16 (transposed into smem)
        {
            int r = tid >> 2, c4 = tid & 3;
            float4 v = *(const float4*)(W + (size_t)(colBase + r) * CDIM + kt * 16 + c4 * 4);
            Wsm[c4 * 4 + 0][r] = v.x;
            Wsm[c4 * 4 + 1][r] = v.y;
            Wsm[c4 * 4 + 2][r] = v.z;
            Wsm[c4 * 4 + 3][r] = v.w;
        }
        __syncthreads();
#pragma unroll
        for (int k = 0; k < 16; ++k) {
            float4 a0 = ((const float4*)Asm[k])[2 * ty];
            float4 a1 = ((const float4*)Asm[k])[2 * ty + 1];
            float4 b0 = ((const float4*)Wsm[k])[tx];
            float a[8] = {a0.x, a0.y, a0.z, a0.w, a1.x, a1.y, a1.z, a1.w};
            float bb[4] = {b0.x, b0.y, b0.z, b0.w};
#pragma unroll
            for (int ii = 0; ii < 8; ii++)
#pragma unroll
                for (int jj = 0; jj < 4; jj++)
                    acc[ii][jj] = fmaf(a[ii], bb[jj], acc[ii][jj]);
        }
        __syncthreads();
    }

    // Epilogue: bias + stash into Cs
    float4 bj = *(const float4*)(bias + colBase + tx * 4);
    float bb[4] = {bj.x, bj.y, bj.z, bj.w};
#pragma unroll
    for (int ii = 0; ii < 8; ii++)
#pragma unroll
        for (int jj = 0; jj < 4; jj++)
            Cs[ty * 8 + ii][tx * 4 + jj] = acc[ii][jj] + bb[jj];
    __syncthreads();

    // Per (row, head) L2 norm over 32 elems. 128 rows x 2 heads = 256 groups.
    {
        int row = tid >> 1, half = tid & 1;
        float s = 0.f;
#pragma unroll
        for (int i = 0; i < 32; i++) {
            float v = Cs[row][half * 32 + i];
            s += v * v;
        }
        scl[row][half] = 1.f / fmaxf(sqrtf(s), 1e-12f);
    }
    __syncthreads();

    // Scatter to [bt, h, l, d]
    for (int e = tid; e < 128 * 64; e += 256) {
        int row = e >> 6, jl = e & 63;
        int j = colBase + jl;
        int h = j >> 5, dd = j & 31;
        int grow = rowBase + row;
        int bt = grow >> 10, l = grow & 1023;
        Out[(((size_t)bt * NHEAD + h) * LSEQ + l) * DHEAD + dd] =
            Cs[row][jl] * scl[row][jl >> 5];
    }
}

// ---------------------------------------------------------------------------
// Kernel 2: flash-style attention per (bth) slice. grid = (8 qtiles, 128 bth),
// 128 threads; each thread owns one q row (d=32 in regs), K/V staged in smem.
// ---------------------------------------------------------------------------
__global__ __launch_bounds__(128) void attn_kernel()
{
    __shared__ float4 Ks[1024];   // 128 rows x 8 float4
    __shared__ float4 Vs[1024];

    const int tid = threadIdx.x;
    const int bth = blockIdx.y;
    const int qt = blockIdx.x;

    const float* Qb = g_qn + (size_t)bth * (LSEQ * DHEAD);
    const float* Kb = g_kn + (size_t)bth * (LSEQ * DHEAD);
    const float* Vb = g_vn + (size_t)bth * (LSEQ * DHEAD);

    const int l = qt * 128 + tid;
    const float sc = 0.17677669529663687f;  // 1/sqrt(32)

    float4 q4[8];
    const float4* qp = (const float4*)(Qb + (size_t)l * DHEAD);
#pragma unroll
    for (int j = 0; j < 8; j++) {
        q4[j] = qp[j];
        q4[j].x *= sc; q4[j].y *= sc; q4[j].z *= sc; q4[j].w *= sc;
    }

    float m = -1e30f, lsum = 0.f;
    float4 o4[8];
#pragma unroll
    for (int j = 0; j < 8; j++) o4[j] = make_float4(0.f, 0.f, 0.f, 0.f);

    for (int kt = 0; kt < 8; ++kt) {
        const float4* kp = (const float4*)(Kb + (size_t)kt * 128 * DHEAD);
        const float4* vp = (const float4*)(Vb + (size_t)kt * 128 * DHEAD);
        __syncthreads();
#pragma unroll
        for (int i = 0; i < 8; i++) {
            Ks[tid + 128 * i] = kp[tid + 128 * i];
            Vs[tid + 128 * i] = vp[tid + 128 * i];
        }
        __syncthreads();

        for (int kk = 0; kk < 128; ++kk) {
            float s0 = 0.f, s1 = 0.f, s2 = 0.f, s3 = 0.f;
#pragma unroll
            for (int j = 0; j < 8; j++) {
                float4 kv = Ks[kk * 8 + j];
                s0 = fmaf(q4[j].x, kv.x, s0);
                s1 = fmaf(q4[j].y, kv.y, s1);
                s2 = fmaf(q4[j].z, kv.z, s2);
                s3 = fmaf(q4[j].w, kv.w, s3);
            }
            float s = (s0 + s1) + (s2 + s3);
            if (s > m) {
                float corr = __expf(m - s);
                m = s;
                lsum *= corr;
#pragma unroll
                for (int j = 0; j < 8; j++) {
                    o4[j].x *= corr; o4[j].y *= corr;
                    o4[j].z *= corr; o4[j].w *= corr;
                }
            }
            float p = __expf(s - m);
            lsum += p;
#pragma unroll
            for (int j = 0; j < 8; j++) {
                float4 vv = Vs[kk * 8 + j];
                o4[j].x = fmaf(p, vv.x, o4[j].x);
                o4[j].y = fmaf(p, vv.y, o4[j].y);
                o4[j].z = fmaf(p, vv.z, o4[j].z);
                o4[j].w = fmaf(p, vv.w, o4[j].w);
            }
        }
    }

    const float inv = 1.f / lsum;
    const int bt = bth >> 3, h = bth & 7;
    float4* op = (float4*)(g_att + (((size_t)bt * LSEQ + l) * CDIM + h * DHEAD));
#pragma unroll
    for (int j = 0; j < 8; j++) {
        float4 o;
        o.x = o4[j].x * inv; o.y = o4[j].y * inv;
        o.z = o4[j].z * inv; o.w = o4[j].w * inv;
        op[j] = o;
    }
}

// ---------------------------------------------------------------------------
// Kernel 3: Out = g_att @ Wm^T + bm + shortcut. Same GEMM tiling, direct
// float4 epilogue (no smem staging needed).
// ---------------------------------------------------------------------------
__global__ __launch_bounds__(256) void final_proj_kernel(
    const float* __restrict__ W, const float* __restrict__ bias,
    const float* __restrict__ shortcut, float* __restrict__ Out)
{
    __shared__ float Asm[16][128];
    __shared__ float Wsm[16][64];

    const float* X = g_att;
    const int tid = threadIdx.x;
    const int tx = tid & 15, ty = tid >> 4;
    const int rowBase = blockIdx.x * 128;
    const int colBase = blockIdx.y * 64;

    float acc[8][4];
#pragma unroll
    for (int i = 0; i < 8; i++)
#pragma unroll
        for (int j = 0; j < 4; j++) acc[i][j] = 0.f;

    for (int kt = 0; kt < 16; ++kt) {
#pragma unroll
        for (int rep = 0; rep < 2; ++rep) {
            int f = tid + rep * 256;
            int r = f >> 2, c4 = f & 3;
            float4 v = *(const float4*)(X + (size_t)(rowBase + r) * CDIM + kt * 16 + c4 * 4);
            Asm[c4 * 4 + 0][r] = v.x;
            Asm[c4 * 4 + 1][r] = v.y;
            Asm[c4 * 4 + 2][r] = v.z;
            Asm[c4 * 4 + 3][r] = v.w;
        }
        {
            int r = tid >> 2, c4 = tid & 3;
            float4 v = *(const float4*)(W + (size_t)(colBase + r) * CDIM + kt * 16 + c4 * 4);
            Wsm[c4 * 4 + 0][r] = v.x;
            Wsm[c4 * 4 + 1][r] = v.y;
            Wsm[c4 * 4 + 2][r] = v.z;
            Wsm[c4 * 4 + 3][r] = v.w;
        }
        __syncthreads();
#pragma unroll
        for (int k = 0; k < 16; ++k) {
            float4 a0 = ((const float4*)Asm[k])[2 * ty];
            float4 a1 = ((const float4*)Asm[k])[2 * ty + 1];
            float4 b0 = ((const float4*)Wsm[k])[tx];
            float a[8] = {a0.x, a0.y, a0.z, a0.w, a1.x, a1.y, a1.z, a1.w};
            float bb[4] = {b0.x, b0.y, b0.z, b0.w};
#pragma unroll
            for (int ii = 0; ii < 8; ii++)
#pragma unroll
                for (int jj = 0; jj < 4; jj++)
                    acc[ii][jj] = fmaf(a[ii], bb[jj], acc[ii][jj]);
        }
        __syncthreads();
    }

    float4 b4 = *(const float4*)(bias + colBase + tx * 4);
#pragma unroll
    for (int ii = 0; ii < 8; ii++) {
        int grow = rowBase + ty * 8 + ii;
        size_t addr = (size_t)grow * CDIM + colBase + tx * 4;
        float4 scv = *(const float4*)(shortcut + addr);
        float4 o;
        o.x = acc[ii][0] + b4.x + scv.x;
        o.y = acc[ii][1] + b4.y + scv.y;
        o.z = acc[ii][2] + b4.z + scv.z;
        o.w = acc[ii][3] + b4.w + scv.w;
        *(float4*)(Out + addr) = o;
    }
}

// ---------------------------------------------------------------------------
extern "C" void kernel_launch(void* const* d_in, const int* in_sizes, int n_in,
                              void* d_out, int out_size)
{
    const float* q  = (const float*)d_in[0];
    const float* k  = (const float*)d_in[1];
    const float* v  = (const float*)d_in[2];
    const float* Wq = (const float*)d_in[3];
    const float* bq = (const float*)d_in[4];
    const float* Wk = (const float*)d_in[5];
    const float* bk = (const float*)d_in[6];
    const float* Wv = (const float*)d_in[7];
    const float* bv = (const float*)d_in[8];
    const float* Wm = (const float*)d_in[9];
    const float* bm = (const float*)d_in[10];
    float* out = (float*)d_out;

    dim3 gg(M_ROWS / 128, CDIM / 64);
    proj_norm_kernel<<<gg, 256>>>(q, Wq, bq, 0);
    proj_norm_kernel<<<gg, 256>>>(k, Wk, bk, 1);
    proj_norm_kernel<<<gg, 256>>>(v, Wv, bv, 2);
    attn_kernel<<<dim3(8, BTH), 128>>>();
    final_proj_kernel<<<gg, 256>>>(Wm, bm, q, out);
}

// round 3
// speedup vs baseline: 2.2508x; 2.2508x over previous
#include <cuda_runtime.h>
#include <cuda_bf16.h>
#include <cstdint>
#include <math.h>

// Problem constants: b=2, t=8, L=1024, c=256, H=8, D=32
#define M_ROWS 16384
#define CDIM   256
#define NHEAD  8
#define DHEAD  32
#define LSEQ   1024
#define BTH    128

// 1/sqrt(32) folded into Q at projection time
#define QSCALE 0.17677669529663687f

// Scratch (device globals)
__device__ __nv_bfloat16 g_q16[4194304];   // [bth, l, d]  (pre-scaled)
__device__ __nv_bfloat16 g_k16[4194304];   // [bth, l, d]
__device__ __nv_bfloat16 g_v16t[4194304];  // [bth, d, l]  (transposed)
__device__ float g_att[4194304];           // [bt, l, c]

// ---------------------------------------------------------------------------
__device__ __forceinline__ uint32_t smem_u32(const void* p) {
    uint32_t a;
    asm("{ .reg .u64 t; cvta.to.shared.u64 t, %1; cvt.u32.u64 %0, t; }" : "=r"(a) : "l"(p));
    return a;
}

#define LDSM_X4(r0, r1, r2, r3, addr) \
    asm volatile("ldmatrix.sync.aligned.m8n8.x4.shared.b16 {%0,%1,%2,%3}, [%4];" \
                 : "=r"(r0), "=r"(r1), "=r"(r2), "=r"(r3) : "r"(addr))
#define LDSM_X2(r0, r1, addr) \
    asm volatile("ldmatrix.sync.aligned.m8n8.x2.shared.b16 {%0,%1}, [%2];" \
                 : "=r"(r0), "=r"(r1) : "r"(addr))

#define MMA_BF16(c0, c1, c2, c3, a0, a1, a2, a3, b0, b1) \
    asm volatile("mma.sync.aligned.m16n8k16.row.col.f32.bf16.bf16.f32 " \
                 "{%0,%1,%2,%3}, {%4,%5,%6,%7}, {%8,%9}, {%0,%1,%2,%3};" \
                 : "+f"(c0), "+f"(c1), "+f"(c2), "+f"(c3) \
                 : "r"(a0), "r"(a1), "r"(a2), "r"(a3), "r"(b0), "r"(b1))

// exp(x) for |x| <= 0.18: 4th-order Taylor (abs err ~1.4e-6)
__device__ __forceinline__ float exp_poly(float x) {
    float p = fmaf(x, 0.04166666667f, 0.16666666667f);
    p = fmaf(x, p, 0.5f);
    p = fmaf(x, p, 1.0f);
    p = fmaf(x, p, 1.0f);
    return p;
}

// ---------------------------------------------------------------------------
// Kernel 1: Y = X @ W^T + bias, split heads, L2-normalize, bf16 epilogue.
// sel: 0=q (scaled, [bth,l,d]), 1=k ([bth,l,d]), 2=v (transposed [bth,d,l])
// ---------------------------------------------------------------------------
__global__ __launch_bounds__(256) void proj_norm_kernel(
    const float* __restrict__ X, const float* __restrict__ W,
    const float* __restrict__ bias, int sel, float extra)
{
    __shared__ float Asm[16][128];
    __shared__ float Wsm[16][64];
    __shared__ float Cs[128][65];
    __shared__ float scl[128][2];

    const int tid = threadIdx.x;
    const int tx = tid & 15, ty = tid >> 4;
    const int rowBase = blockIdx.x * 128;
    const int colBase = blockIdx.y * 64;

    float acc[8][4];
#pragma unroll
    for (int i = 0; i < 8; i++)
#pragma unroll
        for (int j = 0; j < 4; j++) acc[i][j] = 0.f;

    for (int kt = 0; kt < 16; ++kt) {
#pragma unroll
        for (int rep = 0; rep < 2; ++rep) {
            int f = tid + rep * 256;
            int r = f >> 2, c4 = f & 3;
            float4 v = *(const float4*)(X + (size_t)(rowBase + r) * CDIM + kt * 16 + c4 * 4);
            Asm[c4 * 4 + 0][r] = v.x; Asm[c4 * 4 + 1][r] = v.y;
            Asm[c4 * 4 + 2][r] = v.z; Asm[c4 * 4 + 3][r] = v.w;
        }
        {
            int r = tid >> 2, c4 = tid & 3;
            float4 v = *(const float4*)(W + (size_t)(colBase + r) * CDIM + kt * 16 + c4 * 4);
            Wsm[c4 * 4 + 0][r] = v.x; Wsm[c4 * 4 + 1][r] = v.y;
            Wsm[c4 * 4 + 2][r] = v.z; Wsm[c4 * 4 + 3][r] = v.w;
        }
        __syncthreads();
#pragma unroll
        for (int k = 0; k < 16; ++k) {
            float4 a0 = ((const float4*)Asm[k])[2 * ty];
            float4 a1 = ((const float4*)Asm[k])[2 * ty + 1];
            float4 b0 = ((const float4*)Wsm[k])[tx];
            float a[8] = {a0.x, a0.y, a0.z, a0.w, a1.x, a1.y, a1.z, a1.w};
            float bb[4] = {b0.x, b0.y, b0.z, b0.w};
#pragma unroll
            for (int ii = 0; ii < 8; ii++)
#pragma unroll
                for (int jj = 0; jj < 4; jj++)
                    acc[ii][jj] = fmaf(a[ii], bb[jj], acc[ii][jj]);
        }
        __syncthreads();
    }

    float4 bj = *(const float4*)(bias + colBase + tx * 4);
    float bb[4] = {bj.x, bj.y, bj.z, bj.w};
#pragma unroll
    for (int ii = 0; ii < 8; ii++)
#pragma unroll
        for (int jj = 0; jj < 4; jj++)
            Cs[ty * 8 + ii][tx * 4 + jj] = acc[ii][jj] + bb[jj];
    __syncthreads();

    {
        int row = tid >> 1, half = tid & 1;
        float s = 0.f;
#pragma unroll
        for (int i = 0; i < 32; i++) {
            float v = Cs[row][half * 32 + i];
            s += v * v;
        }
        scl[row][half] = extra / fmaxf(sqrtf(s), 1e-12f);
    }
    __syncthreads();

    if (sel != 2) {
        __nv_bfloat16* Out = (sel == 0) ? g_q16 : g_k16;
        for (int e = tid; e < 128 * 64; e += 256) {
            int row = e >> 6, jl = e & 63;
            int j = colBase + jl, h = j >> 5, dd = j & 31;
            int grow = rowBase + row, bt = grow >> 10, l = grow & 1023;
            float val = Cs[row][jl] * scl[row][jl >> 5];
            Out[(((size_t)bt * NHEAD + h) * LSEQ + l) * DHEAD + dd] = __float2bfloat16(val);
        }
    } else {
        for (int e = tid; e < 128 * 64; e += 256) {
            int col = e >> 7, row = e & 127;
            int j = colBase + col, h = j >> 5, dd = j & 31;
            int grow = rowBase + row, bt = grow >> 10, l = grow & 1023;
            float val = Cs[row][col] * scl[row][col >> 5];
            g_v16t[(((size_t)bt * NHEAD + h) * DHEAD + dd) * LSEQ + l] = __float2bfloat16(val);
        }
    }
}

// ---------------------------------------------------------------------------
// Kernel 2: mma.sync bf16 flash attention (no online max: |s| <= 0.177).
// 8 warps; warp w owns q rows [qt*128 + 16w, +16). 8 key tiles of 128.
// ---------------------------------------------------------------------------
__global__ __launch_bounds__(256, 2) void attn_mma_kernel()
{
    __shared__ __nv_bfloat16 Qs[128][40];   // stride 20 words: conflict-free ldsm
    __shared__ __nv_bfloat16 Ks[128][40];
    __shared__ __nv_bfloat16 Vs[32][136];   // stride 68 words

    const int tid = threadIdx.x;
    const int w = tid >> 5, lane = tid & 31;
    const int groupID = lane >> 2, tid4 = lane & 3;
    const int bth = blockIdx.y, qt = blockIdx.x;

    const char* Qg = (const char*)(g_q16 + ((size_t)bth * LSEQ + qt * 128) * DHEAD);
    const char* Kg = (const char*)(g_k16 + (size_t)bth * LSEQ * DHEAD);
    const char* Vg = (const char*)(g_v16t + (size_t)bth * DHEAD * LSEQ);

    // Load Q tile (128 rows x 64B)
#pragma unroll
    for (int i = 0; i < 2; ++i) {
        int f = tid + i * 256;
        int row = f >> 2, part = f & 3;
        *(float4*)(&Qs[row][part * 8]) = *(const float4*)(Qg + row * 64 + part * 16);
    }
    __syncthreads();

    // Q A-fragments (held all kernel)
    uint32_t qa[2][4];
#pragma unroll
    for (int kc = 0; kc < 2; ++kc) {
        int row = w * 16 + (lane & 7) + ((lane & 8) ? 8 : 0);
        int col = kc * 16 + ((lane & 16) ? 8 : 0);
        uint32_t addr = smem_u32(&Qs[row][col]);
        LDSM_X4(qa[kc][0], qa[kc][1], qa[kc][2], qa[kc][3], addr);
    }

    float o[4][4];
#pragma unroll
    for (int i = 0; i < 4; i++)
#pragma unroll
        for (int j = 0; j < 4; j++) o[i][j] = 0.f;
    float ls0 = 0.f, ls1 = 0.f;

    for (int kt = 0; kt < 8; ++kt) {
        __syncthreads();
        // K tile: 128 rows x 64B
#pragma unroll
        for (int i = 0; i < 2; ++i) {
            int f = tid + i * 256;
            int row = f >> 2, part = f & 3;
            *(float4*)(&Ks[row][part * 8]) =
                *(const float4*)(Kg + (size_t)(kt * 128 + row) * 64 + part * 16);
        }
        // Vt tile: 32 rows x 256B
#pragma unroll
        for (int i = 0; i < 2; ++i) {
            int f = tid + i * 256;
            int row = f >> 4, part = f & 15;
            *(float4*)(&Vs[row][part * 8]) =
                *(const float4*)(Vg + (size_t)row * 2048 + kt * 256 + part * 16);
        }
        __syncthreads();

#pragma unroll
        for (int half = 0; half < 2; ++half) {
            // S = Q * K^T for 64 keys
            float s[8][4];
#pragma unroll
            for (int nt = 0; nt < 8; ++nt) {
                int nb = half * 64 + nt * 8;
                uint32_t kb[4];
                uint32_t addr = smem_u32(&Ks[nb + (lane & 7)][(lane >> 3) * 8]);
                LDSM_X4(kb[0], kb[1], kb[2], kb[3], addr);
                s[nt][0] = s[nt][1] = s[nt][2] = s[nt][3] = 0.f;
                MMA_BF16(s[nt][0], s[nt][1], s[nt][2], s[nt][3],
                         qa[0][0], qa[0][1], qa[0][2], qa[0][3], kb[0], kb[1]);
                MMA_BF16(s[nt][0], s[nt][1], s[nt][2], s[nt][3],
                         qa[1][0], qa[1][1], qa[1][2], qa[1][3], kb[2], kb[3]);
            }
            // softmax numerator + pack P into A-fragments
            uint32_t pa[4][4];
#pragma unroll
            for (int nt = 0; nt < 8; ++nt) {
                float p0 = exp_poly(s[nt][0]);
                float p1 = exp_poly(s[nt][1]);
                float p2 = exp_poly(s[nt][2]);
                float p3 = exp_poly(s[nt][3]);
                ls0 += p0 + p1;
                ls1 += p2 + p3;
                uint32_t pk01, pk23;
                asm("cvt.rn.bf16x2.f32 %0, %1, %2;" : "=r"(pk01) : "f"(p1), "f"(p0));
                asm("cvt.rn.bf16x2.f32 %0, %1, %2;" : "=r"(pk23) : "f"(p3), "f"(p2));
                pa[nt >> 1][(nt & 1) * 2 + 0] = pk01;
                pa[nt >> 1][(nt & 1) * 2 + 1] = pk23;
            }
            // O += P * V
#pragma unroll
            for (int dn = 0; dn < 4; ++dn) {
#pragma unroll
                for (int kc = 0; kc < 4; ++kc) {
                    uint32_t vb0, vb1;
                    uint32_t addr = smem_u32(
                        &Vs[dn * 8 + (lane & 7)][half * 64 + kc * 16 + ((lane & 8) ? 8 : 0)]);
                    LDSM_X2(vb0, vb1, addr);
                    MMA_BF16(o[dn][0], o[dn][1], o[dn][2], o[dn][3],
                             pa[kc][0], pa[kc][1], pa[kc][2], pa[kc][3], vb0, vb1);
                }
            }
        }
    }

    // finish row sums (quad reduction)
    ls0 += __shfl_xor_sync(0xffffffffu, ls0, 1);
    ls0 += __shfl_xor_sync(0xffffffffu, ls0, 2);
    ls1 += __shfl_xor_sync(0xffffffffu, ls1, 1);
    ls1 += __shfl_xor_sync(0xffffffffu, ls1, 2);
    const float inv0 = 1.f / ls0, inv1 = 1.f / ls1;

    const int bt = bth >> 3, h = bth & 7;
    const int l0 = qt * 128 + w * 16 + groupID;
#pragma unroll
    for (int dn = 0; dn < 4; ++dn) {
        int col = h * DHEAD + dn * 8 + tid4 * 2;
        float2 v0 = make_float2(o[dn][0] * inv0, o[dn][1] * inv0);
        float2 v1 = make_float2(o[dn][2] * inv1, o[dn][3] * inv1);
        *(float2*)(g_att + ((size_t)bt * LSEQ + l0) * CDIM + col) = v0;
        *(float2*)(g_att + ((size_t)bt * LSEQ + l0 + 8) * CDIM + col) = v1;
    }
}

// ---------------------------------------------------------------------------
// Kernel 3: Out = g_att @ Wm^T + bm + shortcut
// ---------------------------------------------------------------------------
__global__ __launch_bounds__(256) void final_proj_kernel(
    const float* __restrict__ W, const float* __restrict__ bias,
    const float* __restrict__ shortcut, float* __restrict__ Out)
{
    __shared__ float Asm[16][128];
    __shared__ float Wsm[16][64];

    const float* X = g_att;
    const int tid = threadIdx.x;
    const int tx = tid & 15, ty = tid >> 4;
    const int rowBase = blockIdx.x * 128;
    const int colBase = blockIdx.y * 64;

    float acc[8][4];
#pragma unroll
    for (int i = 0; i < 8; i++)
#pragma unroll
        for (int j = 0; j < 4; j++) acc[i][j] = 0.f;

    for (int kt = 0; kt < 16; ++kt) {
#pragma unroll
        for (int rep = 0; rep < 2; ++rep) {
            int f = tid + rep * 256;
            int r = f >> 2, c4 = f & 3;
            float4 v = *(const float4*)(X + (size_t)(rowBase + r) * CDIM + kt * 16 + c4 * 4);
            Asm[c4 * 4 + 0][r] = v.x; Asm[c4 * 4 + 1][r] = v.y;
            Asm[c4 * 4 + 2][r] = v.z; Asm[c4 * 4 + 3][r] = v.w;
        }
        {
            int r = tid >> 2, c4 = tid & 3;
            float4 v = *(const float4*)(W + (size_t)(colBase + r) * CDIM + kt * 16 + c4 * 4);
            Wsm[c4 * 4 + 0][r] = v.x; Wsm[c4 * 4 + 1][r] = v.y;
            Wsm[c4 * 4 + 2][r] = v.z; Wsm[c4 * 4 + 3][r] = v.w;
        }
        __syncthreads();
#pragma unroll
        for (int k = 0; k < 16; ++k) {
            float4 a0 = ((const float4*)Asm[k])[2 * ty];
            float4 a1 = ((const float4*)Asm[k])[2 * ty + 1];
            float4 b0 = ((const float4*)Wsm[k])[tx];
            float a[8] = {a0.x, a0.y, a0.z, a0.w, a1.x, a1.y, a1.z, a1.w};
            float bb[4] = {b0.x, b0.y, b0.z, b0.w};
#pragma unroll
            for (int ii = 0; ii < 8; ii++)
#pragma unroll
                for (int jj = 0; jj < 4; jj++)
                    acc[ii][jj] = fmaf(a[ii], bb[jj], acc[ii][jj]);
        }
        __syncthreads();
    }

    float4 b4 = *(const float4*)(bias + colBase + tx * 4);
#pragma unroll
    for (int ii = 0; ii < 8; ii++) {
        int grow = rowBase + ty * 8 + ii;
        size_t addr = (size_t)grow * CDIM + colBase + tx * 4;
        float4 scv = *(const float4*)(shortcut + addr);
        float4 ov;
        ov.x = acc[ii][0] + b4.x + scv.x;
        ov.y = acc[ii][1] + b4.y + scv.y;
        ov.z = acc[ii][2] + b4.z + scv.z;
        ov.w = acc[ii][3] + b4.w + scv.w;
        *(float4*)(Out + addr) = ov;
    }
}

// ---------------------------------------------------------------------------
extern "C" void kernel_launch(void* const* d_in, const int* in_sizes, int n_in,
                              void* d_out, int out_size)
{
    const float* q  = (const float*)d_in[0];
    const float* k  = (const float*)d_in[1];
    const float* v  = (const float*)d_in[2];
    const float* Wq = (const float*)d_in[3];
    const float* bq = (const float*)d_in[4];
    const float* Wk = (const float*)d_in[5];
    const float* bk = (const float*)d_in[6];
    const float* Wv = (const float*)d_in[7];
    const float* bv = (const float*)d_in[8];
    const float* Wm = (const float*)d_in[9];
    const float* bm = (const float*)d_in[10];
    float* out = (float*)d_out;

    dim3 gg(M_ROWS / 128, CDIM / 64);
    proj_norm_kernel<<<gg, 256>>>(q, Wq, bq, 0, QSCALE);
    proj_norm_kernel<<<gg, 256>>>(k, Wk, bk, 1, 1.0f);
    proj_norm_kernel<<<gg, 256>>>(v, Wv, bv, 2, 1.0f);
    attn_mma_kernel<<<dim3(8, BTH), 256>>>();
    final_proj_kernel<<<gg, 256>>>(Wm, bm, q, out);
}

// round 4
// speedup vs baseline: 5.3642x; 2.3832x over previous
#include <cuda_runtime.h>
#include <cuda_bf16.h>
#include <cstdint>
#include <math.h>

// Problem constants: b=2, t=8, L=1024, c=256, H=8, D=32
#define M_ROWS 16384
#define CDIM   256
#define NHEAD  8
#define DHEAD  32
#define LSEQ   1024
#define BTH    128

// 1/sqrt(32) folded into Q at projection time
#define QSCALE 0.17677669529663687f

// Scratch (device globals)
__device__ __nv_bfloat16 g_q16[4194304];   // [bth, l, d]  (pre-scaled)
__device__ __nv_bfloat16 g_k16[4194304];   // [bth, l, d]
__device__ __nv_bfloat16 g_v16[4194304];   // [bth, l, d]
__device__ __nv_bfloat16 g_att16[4194304]; // [bt, l, c]

// ---------------------------------------------------------------------------
__device__ __forceinline__ uint32_t smem_u32(const void* p) {
    uint32_t a;
    asm("{ .reg .u64 t; cvta.to.shared.u64 t, %1; cvt.u32.u64 %0, t; }" : "=r"(a) : "l"(p));
    return a;
}

#define LDSM_X4(r0, r1, r2, r3, addr) \
    asm volatile("ldmatrix.sync.aligned.m8n8.x4.shared.b16 {%0,%1,%2,%3}, [%4];" \
                 : "=r"(r0), "=r"(r1), "=r"(r2), "=r"(r3) : "r"(addr))
#define LDSM_X2T(r0, r1, addr) \
    asm volatile("ldmatrix.sync.aligned.m8n8.x2.trans.shared.b16 {%0,%1}, [%2];" \
                 : "=r"(r0), "=r"(r1) : "r"(addr))

#define MMA_BF16(c0, c1, c2, c3, a0, a1, a2, a3, b0, b1) \
    asm volatile("mma.sync.aligned.m16n8k16.row.col.f32.bf16.bf16.f32 " \
                 "{%0,%1,%2,%3}, {%4,%5,%6,%7}, {%8,%9}, {%0,%1,%2,%3};" \
                 : "+f"(c0), "+f"(c1), "+f"(c2), "+f"(c3) \
                 : "r"(a0), "r"(a1), "r"(a2), "r"(a3), "r"(b0), "r"(b1))

#define CVT_BF16X2(r, hi, lo) \
    asm("cvt.rn.bf16x2.f32 %0, %1, %2;" : "=r"(r) : "f"(hi), "f"(lo))

// exp(x) for |x| <= 0.18: 4th-order Taylor (abs err ~1.4e-6)
__device__ __forceinline__ float exp_poly(float x) {
    float p = fmaf(x, 0.04166666667f, 0.16666666667f);
    p = fmaf(x, p, 0.5f);
    p = fmaf(x, p, 1.0f);
    p = fmaf(x, p, 1.0f);
    return p;
}

// ---------------------------------------------------------------------------
// Kernel 1: bf16 tensor-core projection. Y = X @ W^T + bias, split heads,
// L2-normalize per head, write bf16 [bth, l, d].
// Tile: 128(M) x 128(N), K-chunks of 32. 8 warps in 4(m) x 2(n);
// warp tile 32x64 = 2 full heads -> warp-local norm.
// ---------------------------------------------------------------------------
__global__ __launch_bounds__(256) void proj_bf16_kernel(
    const float* __restrict__ X, const float* __restrict__ W,
    const float* __restrict__ bias, int sel, float extra)
{
    __shared__ __nv_bfloat16 Xs[128][40];
    __shared__ __nv_bfloat16 Ws[128][40];

    const int tid = threadIdx.x;
    const int w = tid >> 5, lane = tid & 31;
    const int wm = w >> 1, wn = w & 1;
    const int groupID = lane >> 2, tid4 = lane & 3;
    const int rowBase = blockIdx.x * 128;
    const int colBase = blockIdx.y * 128;

    float c[2][8][4];
#pragma unroll
    for (int mt = 0; mt < 2; ++mt)
#pragma unroll
        for (int nt = 0; nt < 8; ++nt)
#pragma unroll
            for (int i = 0; i < 4; ++i) c[mt][nt][i] = 0.f;

    for (int kt = 0; kt < 8; ++kt) {
        __syncthreads();
#pragma unroll
        for (int i = 0; i < 4; ++i) {
            int f = tid + i * 256;
            int row = f >> 3, part = f & 7;
            float4 v = *(const float4*)(X + (size_t)(rowBase + row) * CDIM + kt * 32 + part * 4);
            uint32_t lo, hi;
            CVT_BF16X2(lo, v.y, v.x);
            CVT_BF16X2(hi, v.w, v.z);
            *(uint2*)(&Xs[row][part * 4]) = make_uint2(lo, hi);
        }
#pragma unroll
        for (int i = 0; i < 4; ++i) {
            int f = tid + i * 256;
            int row = f >> 3, part = f & 7;
            float4 v = *(const float4*)(W + (size_t)(colBase + row) * CDIM + kt * 32 + part * 4);
            uint32_t lo, hi;
            CVT_BF16X2(lo, v.y, v.x);
            CVT_BF16X2(hi, v.w, v.z);
            *(uint2*)(&Ws[row][part * 4]) = make_uint2(lo, hi);
        }
        __syncthreads();

        uint32_t a[2][2][4];
#pragma unroll
        for (int mt = 0; mt < 2; ++mt)
#pragma unroll
            for (int ks = 0; ks < 2; ++ks) {
                uint32_t addr = smem_u32(
                    &Xs[wm * 32 + mt * 16 + (lane & 7) + ((lane & 8) ? 8 : 0)]
                       [ks * 16 + ((lane & 16) ? 8 : 0)]);
                LDSM_X4(a[mt][ks][0], a[mt][ks][1], a[mt][ks][2], a[mt][ks][3], addr);
            }
#pragma unroll
        for (int nt = 0; nt < 8; ++nt) {
            uint32_t b[4];
            uint32_t addr = smem_u32(&Ws[wn * 64 + nt * 8 + (lane & 7)][(lane >> 3) * 8]);
            LDSM_X4(b[0], b[1], b[2], b[3], addr);
#pragma unroll
            for (int mt = 0; mt < 2; ++mt) {
                MMA_BF16(c[mt][nt][0], c[mt][nt][1], c[mt][nt][2], c[mt][nt][3],
                         a[mt][0][0], a[mt][0][1], a[mt][0][2], a[mt][0][3], b[0], b[1]);
                MMA_BF16(c[mt][nt][0], c[mt][nt][1], c[mt][nt][2], c[mt][nt][3],
                         a[mt][1][0], a[mt][1][1], a[mt][1][2], a[mt][1][3], b[2], b[3]);
            }
        }
    }

    // Bias (pre-norm)
    float2 bj[8];
#pragma unroll
    for (int nt = 0; nt < 8; ++nt)
        bj[nt] = *(const float2*)(bias + colBase + wn * 64 + nt * 8 + tid4 * 2);
#pragma unroll
    for (int mt = 0; mt < 2; ++mt)
#pragma unroll
        for (int nt = 0; nt < 8; ++nt) {
            c[mt][nt][0] += bj[nt].x; c[mt][nt][1] += bj[nt].y;
            c[mt][nt][2] += bj[nt].x; c[mt][nt][3] += bj[nt].y;
        }

    __nv_bfloat16* Out = (sel == 0) ? g_q16 : (sel == 1) ? g_k16 : g_v16;

#pragma unroll
    for (int mt = 0; mt < 2; ++mt) {
        float ss[2][2];  // [rowHalf][head]
        ss[0][0] = ss[0][1] = ss[1][0] = ss[1][1] = 0.f;
#pragma unroll
        for (int nt = 0; nt < 8; ++nt) {
            int hd = nt >> 2;
            ss[0][hd] += c[mt][nt][0] * c[mt][nt][0] + c[mt][nt][1] * c[mt][nt][1];
            ss[1][hd] += c[mt][nt][2] * c[mt][nt][2] + c[mt][nt][3] * c[mt][nt][3];
        }
        float scl[2][2];
#pragma unroll
        for (int rh = 0; rh < 2; ++rh)
#pragma unroll
            for (int hd = 0; hd < 2; ++hd) {
                float s = ss[rh][hd];
                s += __shfl_xor_sync(0xffffffffu, s, 1);
                s += __shfl_xor_sync(0xffffffffu, s, 2);
                scl[rh][hd] = extra / fmaxf(sqrtf(s), 1e-12f);
            }
#pragma unroll
        for (int rh = 0; rh < 2; ++rh) {
            int grow = rowBase + wm * 32 + mt * 16 + groupID + rh * 8;
            int bt = grow >> 10, l = grow & 1023;
#pragma unroll
            for (int nt = 0; nt < 8; ++nt) {
                int j = colBase + wn * 64 + nt * 8 + tid4 * 2;
                int h = j >> 5, dd = j & 31;
                float sc = scl[rh][nt >> 2];
                uint32_t pk;
                CVT_BF16X2(pk, c[mt][nt][rh * 2 + 1] * sc, c[mt][nt][rh * 2 + 0] * sc);
                *(uint32_t*)(Out + (((size_t)bt * NHEAD + h) * LSEQ + l) * DHEAD + dd) = pk;
            }
        }
    }
}

// ---------------------------------------------------------------------------
// Kernel 2: mma.sync bf16 flash attention (no online max: |s| <= 0.177).
// V loaded in [l, d] layout; PV B-frags via ldmatrix.trans.
// Writes bf16 g_att16.
// ---------------------------------------------------------------------------
__global__ __launch_bounds__(256, 2) void attn_mma_kernel()
{
    __shared__ __nv_bfloat16 Qs[128][40];
    __shared__ __nv_bfloat16 Ks[128][40];
    __shared__ __nv_bfloat16 Vs[128][40];

    const int tid = threadIdx.x;
    const int w = tid >> 5, lane = tid & 31;
    const int groupID = lane >> 2, tid4 = lane & 3;
    const int bth = blockIdx.y, qt = blockIdx.x;

    const char* Qg = (const char*)(g_q16 + ((size_t)bth * LSEQ + qt * 128) * DHEAD);
    const char* Kg = (const char*)(g_k16 + (size_t)bth * LSEQ * DHEAD);
    const char* Vg = (const char*)(g_v16 + (size_t)bth * LSEQ * DHEAD);

#pragma unroll
    for (int i = 0; i < 2; ++i) {
        int f = tid + i * 256;
        int row = f >> 2, part = f & 3;
        *(float4*)(&Qs[row][part * 8]) = *(const float4*)(Qg + row * 64 + part * 16);
    }
    __syncthreads();

    uint32_t qa[2][4];
#pragma unroll
    for (int kc = 0; kc < 2; ++kc) {
        int row = w * 16 + (lane & 7) + ((lane & 8) ? 8 : 0);
        int col = kc * 16 + ((lane & 16) ? 8 : 0);
        uint32_t addr = smem_u32(&Qs[row][col]);
        LDSM_X4(qa[kc][0], qa[kc][1], qa[kc][2], qa[kc][3], addr);
    }

    float o[4][4];
#pragma unroll
    for (int i = 0; i < 4; i++)
#pragma unroll
        for (int j = 0; j < 4; j++) o[i][j] = 0.f;
    float ls0 = 0.f, ls1 = 0.f;

    for (int kt = 0; kt < 8; ++kt) {
        __syncthreads();
#pragma unroll
        for (int i = 0; i < 2; ++i) {
            int f = tid + i * 256;
            int row = f >> 2, part = f & 3;
            *(float4*)(&Ks[row][part * 8]) =
                *(const float4*)(Kg + (size_t)(kt * 128 + row) * 64 + part * 16);
            *(float4*)(&Vs[row][part * 8]) =
                *(const float4*)(Vg + (size_t)(kt * 128 + row) * 64 + part * 16);
        }
        __syncthreads();

#pragma unroll
        for (int half = 0; half < 2; ++half) {
            float s[8][4];
#pragma unroll
            for (int nt = 0; nt < 8; ++nt) {
                int nb = half * 64 + nt * 8;
                uint32_t kb[4];
                uint32_t addr = smem_u32(&Ks[nb + (lane & 7)][(lane >> 3) * 8]);
                LDSM_X4(kb[0], kb[1], kb[2], kb[3], addr);
                s[nt][0] = s[nt][1] = s[nt][2] = s[nt][3] = 0.f;
                MMA_BF16(s[nt][0], s[nt][1], s[nt][2], s[nt][3],
                         qa[0][0], qa[0][1], qa[0][2], qa[0][3], kb[0], kb[1]);
                MMA_BF16(s[nt][0], s[nt][1], s[nt][2], s[nt][3],
                         qa[1][0], qa[1][1], qa[1][2], qa[1][3], kb[2], kb[3]);
            }
            uint32_t pa[4][4];
#pragma unroll
            for (int nt = 0; nt < 8; ++nt) {
                float p0 = exp_poly(s[nt][0]);
                float p1 = exp_poly(s[nt][1]);
                float p2 = exp_poly(s[nt][2]);
                float p3 = exp_poly(s[nt][3]);
                ls0 += p0 + p1;
                ls1 += p2 + p3;
                uint32_t pk01, pk23;
                CVT_BF16X2(pk01, p1, p0);
                CVT_BF16X2(pk23, p3, p2);
                pa[nt >> 1][(nt & 1) * 2 + 0] = pk01;
                pa[nt >> 1][(nt & 1) * 2 + 1] = pk23;
            }
#pragma unroll
            for (int dn = 0; dn < 4; ++dn) {
#pragma unroll
                for (int kc = 0; kc < 4; ++kc) {
                    uint32_t vb0, vb1;
                    uint32_t addr = smem_u32(
                        &Vs[half * 64 + kc * 16 + (lane & 15)][dn * 8]);
                    LDSM_X2T(vb0, vb1, addr);
                    MMA_BF16(o[dn][0], o[dn][1], o[dn][2], o[dn][3],
                             pa[kc][0], pa[kc][1], pa[kc][2], pa[kc][3], vb0, vb1);
                }
            }
        }
    }

    ls0 += __shfl_xor_sync(0xffffffffu, ls0, 1);
    ls0 += __shfl_xor_sync(0xffffffffu, ls0, 2);
    ls1 += __shfl_xor_sync(0xffffffffu, ls1, 1);
    ls1 += __shfl_xor_sync(0xffffffffu, ls1, 2);
    const float inv0 = 1.f / ls0, inv1 = 1.f / ls1;

    const int bt = bth >> 3, h = bth & 7;
    const int l0 = qt * 128 + w * 16 + groupID;
#pragma unroll
    for (int dn = 0; dn < 4; ++dn) {
        int col = h * DHEAD + dn * 8 + tid4 * 2;
        uint32_t pk0, pk1;
        CVT_BF16X2(pk0, o[dn][1] * inv0, o[dn][0] * inv0);
        CVT_BF16X2(pk1, o[dn][3] * inv1, o[dn][2] * inv1);
        *(uint32_t*)(g_att16 + ((size_t)bt * LSEQ + l0) * CDIM + col) = pk0;
        *(uint32_t*)(g_att16 + ((size_t)bt * LSEQ + l0 + 8) * CDIM + col) = pk1;
    }
}

// ---------------------------------------------------------------------------
// Kernel 3: Out = g_att16 @ Wm^T + bm + shortcut (fp32 out).
// Same tiling as proj kernel; X already bf16.
// ---------------------------------------------------------------------------
__global__ __launch_bounds__(256) void final_bf16_kernel(
    const float* __restrict__ W, const float* __restrict__ bias,
    const float* __restrict__ shortcut, float* __restrict__ Out)
{
    __shared__ __nv_bfloat16 Xs[128][40];
    __shared__ __nv_bfloat16 Ws[128][40];

    const int tid = threadIdx.x;
    const int w = tid >> 5, lane = tid & 31;
    const int wm = w >> 1, wn = w & 1;
    const int groupID = lane >> 2, tid4 = lane & 3;
    const int rowBase = blockIdx.x * 128;
    const int colBase = blockIdx.y * 128;

    float c[2][8][4];
#pragma unroll
    for (int mt = 0; mt < 2; ++mt)
#pragma unroll
        for (int nt = 0; nt < 8; ++nt)
#pragma unroll
            for (int i = 0; i < 4; ++i) c[mt][nt][i] = 0.f;

    for (int kt = 0; kt < 8; ++kt) {
        __syncthreads();
#pragma unroll
        for (int i = 0; i < 2; ++i) {
            int f = tid + i * 256;
            int row = f >> 2, part = f & 3;
            *(uint4*)(&Xs[row][part * 8]) =
                *(const uint4*)(g_att16 + (size_t)(rowBase + row) * CDIM + kt * 32 + part * 8);
        }
#pragma unroll
        for (int i = 0; i < 4; ++i) {
            int f = tid + i * 256;
            int row = f >> 3, part = f & 7;
            float4 v = *(const float4*)(W + (size_t)(colBase + row) * CDIM + kt * 32 + part * 4);
            uint32_t lo, hi;
            CVT_BF16X2(lo, v.y, v.x);
            CVT_BF16X2(hi, v.w, v.z);
            *(uint2*)(&Ws[row][part * 4]) = make_uint2(lo, hi);
        }
        __syncthreads();

        uint32_t a[2][2][4];
#pragma unroll
        for (int mt = 0; mt < 2; ++mt)
#pragma unroll
            for (int ks = 0; ks < 2; ++ks) {
                uint32_t addr = smem_u32(
                    &Xs[wm * 32 + mt * 16 + (lane & 7) + ((lane & 8) ? 8 : 0)]
                       [ks * 16 + ((lane & 16) ? 8 : 0)]);
                LDSM_X4(a[mt][ks][0], a[mt][ks][1], a[mt][ks][2], a[mt][ks][3], addr);
            }
#pragma unroll
        for (int nt = 0; nt < 8; ++nt) {
            uint32_t b[4];
            uint32_t addr = smem_u32(&Ws[wn * 64 + nt * 8 + (lane & 7)][(lane >> 3) * 8]);
            LDSM_X4(b[0], b[1], b[2], b[3], addr);
#pragma unroll
            for (int mt = 0; mt < 2; ++mt) {
                MMA_BF16(c[mt][nt][0], c[mt][nt][1], c[mt][nt][2], c[mt][nt][3],
                         a[mt][0][0], a[mt][0][1], a[mt][0][2], a[mt][0][3], b[0], b[1]);
                MMA_BF16(c[mt][nt][0], c[mt][nt][1], c[mt][nt][2], c[mt][nt][3],
                         a[mt][1][0], a[mt][1][1], a[mt][1][2], a[mt][1][3], b[2], b[3]);
            }
        }
    }

    float2 bj[8];
#pragma unroll
    for (int nt = 0; nt < 8; ++nt)
        bj[nt] = *(const float2*)(bias + colBase + wn * 64 + nt * 8 + tid4 * 2);

#pragma unroll
    for (int mt = 0; mt < 2; ++mt)
#pragma unroll
        for (int rh = 0; rh < 2; ++rh) {
            int grow = rowBase + wm * 32 + mt * 16 + groupID + rh * 8;
#pragma unroll
            for (int nt = 0; nt < 8; ++nt) {
                int j = colBase + wn * 64 + nt * 8 + tid4 * 2;
                size_t addr = (size_t)grow * CDIM + j;
                float2 sc = *(const float2*)(shortcut + addr);
                float2 ov;
                ov.x = c[mt][nt][rh * 2 + 0] + bj[nt].x + sc.x;
                ov.y = c[mt][nt][rh * 2 + 1] + bj[nt].y + sc.y;
                *(float2*)(Out + addr) = ov;
            }
        }
}

// ---------------------------------------------------------------------------
extern "C" void kernel_launch(void* const* d_in, const int* in_sizes, int n_in,
                              void* d_out, int out_size)
{
    const float* q  = (const float*)d_in[0];
    const float* k  = (const float*)d_in[1];
    const float* v  = (const float*)d_in[2];
    const float* Wq = (const float*)d_in[3];
    const float* bq = (const float*)d_in[4];
    const float* Wk = (const float*)d_in[5];
    const float* bk = (const float*)d_in[6];
    const float* Wv = (const float*)d_in[7];
    const float* bv = (const float*)d_in[8];
    const float* Wm = (const float*)d_in[9];
    const float* bm = (const float*)d_in[10];
    float* out = (float*)d_out;

    dim3 gg(M_ROWS / 128, CDIM / 128);
    proj_bf16_kernel<<<gg, 256>>>(q, Wq, bq, 0, QSCALE);
    proj_bf16_kernel<<<gg, 256>>>(k, Wk, bk, 1, 1.0f);
    proj_bf16_kernel<<<gg, 256>>>(v, Wv, bv, 2, 1.0f);
    attn_mma_kernel<<<dim3(8, BTH), 256>>>();
    final_bf16_kernel<<<gg, 256>>>(Wm, bm, q, out);
}

// round 5
// speedup vs baseline: 5.9732x; 1.1135x over previous
#include <cuda_runtime.h>
#include <cuda_bf16.h>
#include <cstdint>
#include <math.h>

// Problem constants: b=2, t=8, L=1024, c=256, H=8, D=32
#define M_ROWS 16384
#define CDIM   256
#define NHEAD  8
#define DHEAD  32
#define LSEQ   1024
#define BTH    128

// 1/sqrt(32) folded into Q at projection time
#define QSCALE 0.17677669529663687f

// Scratch (device globals)
__device__ __nv_bfloat16 g_q16[4194304];   // [bth, l, d]  (pre-scaled)
__device__ __nv_bfloat16 g_k16[4194304];   // [bth, l, d]
__device__ __nv_bfloat16 g_v16[4194304];   // [bth, l, d]
__device__ __nv_bfloat16 g_att16[4194304]; // [bt, l, c]

// ---------------------------------------------------------------------------
__device__ __forceinline__ uint32_t smem_u32(const void* p) {
    uint32_t a;
    asm("{ .reg .u64 t; cvta.to.shared.u64 t, %1; cvt.u32.u64 %0, t; }" : "=r"(a) : "l"(p));
    return a;
}

#define LDSM_X4(r0, r1, r2, r3, addr) \
    asm volatile("ldmatrix.sync.aligned.m8n8.x4.shared.b16 {%0,%1,%2,%3}, [%4];" \
                 : "=r"(r0), "=r"(r1), "=r"(r2), "=r"(r3) : "r"(addr))
#define LDSM_X4T(r0, r1, r2, r3, addr) \
    asm volatile("ldmatrix.sync.aligned.m8n8.x4.trans.shared.b16 {%0,%1,%2,%3}, [%4];" \
                 : "=r"(r0), "=r"(r1), "=r"(r2), "=r"(r3) : "r"(addr))

#define MMA_BF16(c0, c1, c2, c3, a0, a1, a2, a3, b0, b1) \
    asm volatile("mma.sync.aligned.m16n8k16.row.col.f32.bf16.bf16.f32 " \
                 "{%0,%1,%2,%3}, {%4,%5,%6,%7}, {%8,%9}, {%0,%1,%2,%3};" \
                 : "+f"(c0), "+f"(c1), "+f"(c2), "+f"(c3) \
                 : "r"(a0), "r"(a1), "r"(a2), "r"(a3), "r"(b0), "r"(b1))

#define CVT_BF16X2(r, hi, lo) \
    asm("cvt.rn.bf16x2.f32 %0, %1, %2;" : "=r"(r) : "f"(hi), "f"(lo))

#define CP16(dst, src) \
    asm volatile("cp.async.cg.shared.global [%0], [%1], 16;" :: "r"(dst), "l"(src))
#define CP_COMMIT() asm volatile("cp.async.commit_group;")
#define CP_WAIT(n)  asm volatile("cp.async.wait_group %0;" :: "n"(n))

// exp(x) for |x| <= 0.18: 4th-order Taylor (abs err ~1.4e-6)
__device__ __forceinline__ float exp_poly(float x) {
    float p = fmaf(x, 0.04166666667f, 0.16666666667f);
    p = fmaf(x, p, 0.5f);
    p = fmaf(x, p, 1.0f);
    p = fmaf(x, p, 1.0f);
    return p;
}

// ---------------------------------------------------------------------------
// Kernel 1: merged q/k/v bf16 tensor-core projection (grid.z selects which).
// Y = X @ W^T + bias, split heads, L2-normalize per head, bf16 [bth, l, d].
// Tile 128x128, K-chunks 32; warp tile 32x64 = 2 heads -> warp-local norm.
// ---------------------------------------------------------------------------
__global__ __launch_bounds__(256) void qkv_proj_kernel(
    const float* __restrict__ q, const float* __restrict__ k, const float* __restrict__ v,
    const float* __restrict__ Wq, const float* __restrict__ bq,
    const float* __restrict__ Wk, const float* __restrict__ bk,
    const float* __restrict__ Wv, const float* __restrict__ bv)
{
    __shared__ __nv_bfloat16 Xs[128][40];
    __shared__ __nv_bfloat16 Ws[128][40];

    const int sel = blockIdx.z;
    const float* X = (sel == 0) ? q : (sel == 1) ? k : v;
    const float* W = (sel == 0) ? Wq : (sel == 1) ? Wk : Wv;
    const float* bias = (sel == 0) ? bq : (sel == 1) ? bk : bv;
    const float extra = (sel == 0) ? QSCALE : 1.0f;
    __nv_bfloat16* Out = (sel == 0) ? g_q16 : (sel == 1) ? g_k16 : g_v16;

    const int tid = threadIdx.x;
    const int w = tid >> 5, lane = tid & 31;
    const int wm = w >> 1, wn = w & 1;
    const int groupID = lane >> 2, tid4 = lane & 3;
    const int rowBase = blockIdx.x * 128;
    const int colBase = blockIdx.y * 128;

    float c[2][8][4];
#pragma unroll
    for (int mt = 0; mt < 2; ++mt)
#pragma unroll
        for (int nt = 0; nt < 8; ++nt)
#pragma unroll
            for (int i = 0; i < 4; ++i) c[mt][nt][i] = 0.f;

    for (int kt = 0; kt < 8; ++kt) {
        __syncthreads();
#pragma unroll
        for (int i = 0; i < 4; ++i) {
            int f = tid + i * 256;
            int row = f >> 3, part = f & 7;
            float4 vx = *(const float4*)(X + (size_t)(rowBase + row) * CDIM + kt * 32 + part * 4);
            uint32_t lo, hi;
            CVT_BF16X2(lo, vx.y, vx.x);
            CVT_BF16X2(hi, vx.w, vx.z);
            *(uint2*)(&Xs[row][part * 4]) = make_uint2(lo, hi);
        }
#pragma unroll
        for (int i = 0; i < 4; ++i) {
            int f = tid + i * 256;
            int row = f >> 3, part = f & 7;
            float4 vx = *(const float4*)(W + (size_t)(colBase + row) * CDIM + kt * 32 + part * 4);
            uint32_t lo, hi;
            CVT_BF16X2(lo, vx.y, vx.x);
            CVT_BF16X2(hi, vx.w, vx.z);
            *(uint2*)(&Ws[row][part * 4]) = make_uint2(lo, hi);
        }
        __syncthreads();

        uint32_t a[2][2][4];
#pragma unroll
        for (int mt = 0; mt < 2; ++mt)
#pragma unroll
            for (int ks = 0; ks < 2; ++ks) {
                uint32_t addr = smem_u32(
                    &Xs[wm * 32 + mt * 16 + (lane & 7) + ((lane & 8) ? 8 : 0)]
                       [ks * 16 + ((lane & 16) ? 8 : 0)]);
                LDSM_X4(a[mt][ks][0], a[mt][ks][1], a[mt][ks][2], a[mt][ks][3], addr);
            }
#pragma unroll
        for (int nt = 0; nt < 8; ++nt) {
            uint32_t b[4];
            uint32_t addr = smem_u32(&Ws[wn * 64 + nt * 8 + (lane & 7)][(lane >> 3) * 8]);
            LDSM_X4(b[0], b[1], b[2], b[3], addr);
#pragma unroll
            for (int mt = 0; mt < 2; ++mt) {
                MMA_BF16(c[mt][nt][0], c[mt][nt][1], c[mt][nt][2], c[mt][nt][3],
                         a[mt][0][0], a[mt][0][1], a[mt][0][2], a[mt][0][3], b[0], b[1]);
                MMA_BF16(c[mt][nt][0], c[mt][nt][1], c[mt][nt][2], c[mt][nt][3],
                         a[mt][1][0], a[mt][1][1], a[mt][1][2], a[mt][1][3], b[2], b[3]);
            }
        }
    }

    float2 bj[8];
#pragma unroll
    for (int nt = 0; nt < 8; ++nt)
        bj[nt] = *(const float2*)(bias + colBase + wn * 64 + nt * 8 + tid4 * 2);
#pragma unroll
    for (int mt = 0; mt < 2; ++mt)
#pragma unroll
        for (int nt = 0; nt < 8; ++nt) {
            c[mt][nt][0] += bj[nt].x; c[mt][nt][1] += bj[nt].y;
            c[mt][nt][2] += bj[nt].x; c[mt][nt][3] += bj[nt].y;
        }

#pragma unroll
    for (int mt = 0; mt < 2; ++mt) {
        float ss[2][2];
        ss[0][0] = ss[0][1] = ss[1][0] = ss[1][1] = 0.f;
#pragma unroll
        for (int nt = 0; nt < 8; ++nt) {
            int hd = nt >> 2;
            ss[0][hd] += c[mt][nt][0] * c[mt][nt][0] + c[mt][nt][1] * c[mt][nt][1];
            ss[1][hd] += c[mt][nt][2] * c[mt][nt][2] + c[mt][nt][3] * c[mt][nt][3];
        }
        float scl[2][2];
#pragma unroll
        for (int rh = 0; rh < 2; ++rh)
#pragma unroll
            for (int hd = 0; hd < 2; ++hd) {
                float s = ss[rh][hd];
                s += __shfl_xor_sync(0xffffffffu, s, 1);
                s += __shfl_xor_sync(0xffffffffu, s, 2);
                scl[rh][hd] = extra / fmaxf(sqrtf(s), 1e-12f);
            }
#pragma unroll
        for (int rh = 0; rh < 2; ++rh) {
            int grow = rowBase + wm * 32 + mt * 16 + groupID + rh * 8;
            int bt = grow >> 10, l = grow & 1023;
#pragma unroll
            for (int nt = 0; nt < 8; ++nt) {
                int j = colBase + wn * 64 + nt * 8 + tid4 * 2;
                int h = j >> 5, dd = j & 31;
                float sc = scl[rh][nt >> 2];
                uint32_t pk;
                CVT_BF16X2(pk, c[mt][nt][rh * 2 + 1] * sc, c[mt][nt][rh * 2 + 0] * sc);
                *(uint32_t*)(Out + (((size_t)bt * NHEAD + h) * LSEQ + l) * DHEAD + dd) = pk;
            }
        }
    }
}

// ---------------------------------------------------------------------------
// Kernel 2: bf16 flash attention, cp.async double-buffered K/V,
// ldmatrix.x4.trans for V. No online max (|s| <= 0.177).
// ---------------------------------------------------------------------------
__global__ __launch_bounds__(256, 2) void attn_mma_kernel()
{
    __shared__ __nv_bfloat16 sK[2][128][40];
    __shared__ __nv_bfloat16 sV[2][128][40];

    const int tid = threadIdx.x;
    const int w = tid >> 5, lane = tid & 31;
    const int groupID = lane >> 2, tid4 = lane & 3;
    const int bth = blockIdx.y, qt = blockIdx.x;

    const char* Qg = (const char*)(g_q16 + ((size_t)bth * LSEQ + qt * 128) * DHEAD);
    const char* Kg = (const char*)(g_k16 + (size_t)bth * LSEQ * DHEAD);
    const char* Vg = (const char*)(g_v16 + (size_t)bth * LSEQ * DHEAD);

    // Stage Q through sK[0] (before pipeline starts)
#pragma unroll
    for (int i = 0; i < 2; ++i) {
        int f = tid + i * 256;
        int row = f >> 2, part = f & 3;
        *(float4*)(&sK[0][row][part * 8]) = *(const float4*)(Qg + row * 64 + part * 16);
    }
    __syncthreads();

    uint32_t qa[2][4];
#pragma unroll
    for (int kc = 0; kc < 2; ++kc) {
        int row = w * 16 + (lane & 7) + ((lane & 8) ? 8 : 0);
        int col = kc * 16 + ((lane & 16) ? 8 : 0);
        uint32_t addr = smem_u32(&sK[0][row][col]);
        LDSM_X4(qa[kc][0], qa[kc][1], qa[kc][2], qa[kc][3], addr);
    }
    __syncthreads();   // all warps done reading Q from sK[0]

    // cp.async tile loader: K+V tile kt into buffer b (one commit group)
    const int r0 = tid >> 2, p0 = tid & 3;
    const int r1 = (tid + 256) >> 2, p1 = tid & 3;
    {
        // prologue: tile 0 -> buf 0
        CP16(smem_u32(&sK[0][r0][p0 * 8]), Kg + (size_t)r0 * 64 + p0 * 16);
        CP16(smem_u32(&sK[0][r1][p1 * 8]), Kg + (size_t)r1 * 64 + p1 * 16);
        CP16(smem_u32(&sV[0][r0][p0 * 8]), Vg + (size_t)r0 * 64 + p0 * 16);
        CP16(smem_u32(&sV[0][r1][p1 * 8]), Vg + (size_t)r1 * 64 + p1 * 16);
        CP_COMMIT();
    }

    float o[4][4];
#pragma unroll
    for (int i = 0; i < 4; i++)
#pragma unroll
        for (int j = 0; j < 4; j++) o[i][j] = 0.f;
    float ls0 = 0.f, ls1 = 0.f;

    for (int kt = 0; kt < 8; ++kt) {
        const int cb = kt & 1;
        if (kt < 7) {
            const int nb = (kt + 1) & 1;
            const char* Kt = Kg + (size_t)(kt + 1) * 128 * 64;
            const char* Vt = Vg + (size_t)(kt + 1) * 128 * 64;
            CP16(smem_u32(&sK[nb][r0][p0 * 8]), Kt + (size_t)r0 * 64 + p0 * 16);
            CP16(smem_u32(&sK[nb][r1][p1 * 8]), Kt + (size_t)r1 * 64 + p1 * 16);
            CP16(smem_u32(&sV[nb][r0][p0 * 8]), Vt + (size_t)r0 * 64 + p0 * 16);
            CP16(smem_u32(&sV[nb][r1][p1 * 8]), Vt + (size_t)r1 * 64 + p1 * 16);
            CP_COMMIT();
            CP_WAIT(1);
        } else {
            CP_WAIT(0);
        }
        __syncthreads();

#pragma unroll
        for (int half = 0; half < 2; ++half) {
            // S = Q * K^T for 64 keys
            float s[8][4];
#pragma unroll
            for (int nt = 0; nt < 8; ++nt) {
                int nb = half * 64 + nt * 8;
                uint32_t kb[4];
                uint32_t addr = smem_u32(&sK[cb][nb + (lane & 7)][(lane >> 3) * 8]);
                LDSM_X4(kb[0], kb[1], kb[2], kb[3], addr);
                s[nt][0] = s[nt][1] = s[nt][2] = s[nt][3] = 0.f;
                MMA_BF16(s[nt][0], s[nt][1], s[nt][2], s[nt][3],
                         qa[0][0], qa[0][1], qa[0][2], qa[0][3], kb[0], kb[1]);
                MMA_BF16(s[nt][0], s[nt][1], s[nt][2], s[nt][3],
                         qa[1][0], qa[1][1], qa[1][2], qa[1][3], kb[2], kb[3]);
            }
            // softmax numerator + pack P into A-fragments
            uint32_t pa[4][4];
#pragma unroll
            for (int nt = 0; nt < 8; ++nt) {
                float p0f = exp_poly(s[nt][0]);
                float p1f = exp_poly(s[nt][1]);
                float p2f = exp_poly(s[nt][2]);
                float p3f = exp_poly(s[nt][3]);
                ls0 += p0f + p1f;
                ls1 += p2f + p3f;
                uint32_t pk01, pk23;
                CVT_BF16X2(pk01, p1f, p0f);
                CVT_BF16X2(pk23, p3f, p2f);
                pa[nt >> 1][(nt & 1) * 2 + 0] = pk01;
                pa[nt >> 1][(nt & 1) * 2 + 1] = pk23;
            }
            // O += P * V ; x4.trans covers two d-groups per ldmatrix
#pragma unroll
            for (int dp = 0; dp < 2; ++dp) {
#pragma unroll
                for (int kc = 0; kc < 4; ++kc) {
                    uint32_t vb[4];
                    uint32_t addr = smem_u32(
                        &sV[cb][half * 64 + kc * 16 + (lane & 15)]
                           [dp * 16 + ((lane & 16) ? 8 : 0)]);
                    LDSM_X4T(vb[0], vb[1], vb[2], vb[3], addr);
                    MMA_BF16(o[2 * dp][0], o[2 * dp][1], o[2 * dp][2], o[2 * dp][3],
                             pa[kc][0], pa[kc][1], pa[kc][2], pa[kc][3], vb[0], vb[1]);
                    MMA_BF16(o[2 * dp + 1][0], o[2 * dp + 1][1], o[2 * dp + 1][2], o[2 * dp + 1][3],
                             pa[kc][0], pa[kc][1], pa[kc][2], pa[kc][3], vb[2], vb[3]);
                }
            }
        }
        __syncthreads();
    }

    ls0 += __shfl_xor_sync(0xffffffffu, ls0, 1);
    ls0 += __shfl_xor_sync(0xffffffffu, ls0, 2);
    ls1 += __shfl_xor_sync(0xffffffffu, ls1, 1);
    ls1 += __shfl_xor_sync(0xffffffffu, ls1, 2);
    const float inv0 = 1.f / ls0, inv1 = 1.f / ls1;

    const int bt = bth >> 3, h = bth & 7;
    const int l0 = qt * 128 + w * 16 + groupID;
#pragma unroll
    for (int dn = 0; dn < 4; ++dn) {
        int col = h * DHEAD + dn * 8 + tid4 * 2;
        uint32_t pk0, pk1;
        CVT_BF16X2(pk0, o[dn][1] * inv0, o[dn][0] * inv0);
        CVT_BF16X2(pk1, o[dn][3] * inv1, o[dn][2] * inv1);
        *(uint32_t*)(g_att16 + ((size_t)bt * LSEQ + l0) * CDIM + col) = pk0;
        *(uint32_t*)(g_att16 + ((size_t)bt * LSEQ + l0 + 8) * CDIM + col) = pk1;
    }
}

// ---------------------------------------------------------------------------
// Kernel 3: Out = g_att16 @ Wm^T + bm + shortcut (fp32 out).
// ---------------------------------------------------------------------------
__global__ __launch_bounds__(256) void final_bf16_kernel(
    const float* __restrict__ W, const float* __restrict__ bias,
    const float* __restrict__ shortcut, float* __restrict__ Out)
{
    __shared__ __nv_bfloat16 Xs[128][40];
    __shared__ __nv_bfloat16 Ws[128][40];

    const int tid = threadIdx.x;
    const int w = tid >> 5, lane = tid & 31;
    const int wm = w >> 1, wn = w & 1;
    const int groupID = lane >> 2, tid4 = lane & 3;
    const int rowBase = blockIdx.x * 128;
    const int colBase = blockIdx.y * 128;

    float c[2][8][4];
#pragma unroll
    for (int mt = 0; mt < 2; ++mt)
#pragma unroll
        for (int nt = 0; nt < 8; ++nt)
#pragma unroll
            for (int i = 0; i < 4; ++i) c[mt][nt][i] = 0.f;

    for (int kt = 0; kt < 8; ++kt) {
        __syncthreads();
#pragma unroll
        for (int i = 0; i < 2; ++i) {
            int f = tid + i * 256;
            int row = f >> 2, part = f & 3;
            *(uint4*)(&Xs[row][part * 8]) =
                *(const uint4*)(g_att16 + (size_t)(rowBase + row) * CDIM + kt * 32 + part * 8);
        }
#pragma unroll
        for (int i = 0; i < 4; ++i) {
            int f = tid + i * 256;
            int row = f >> 3, part = f & 7;
            float4 vx = *(const float4*)(W + (size_t)(colBase + row) * CDIM + kt * 32 + part * 4);
            uint32_t lo, hi;
            CVT_BF16X2(lo, vx.y, vx.x);
            CVT_BF16X2(hi, vx.w, vx.z);
            *(uint2*)(&Ws[row][part * 4]) = make_uint2(lo, hi);
        }
        __syncthreads();

        uint32_t a[2][2][4];
#pragma unroll
        for (int mt = 0; mt < 2; ++mt)
#pragma unroll
            for (int ks = 0; ks < 2; ++ks) {
                uint32_t addr = smem_u32(
                    &Xs[wm * 32 + mt * 16 + (lane & 7) + ((lane & 8) ? 8 : 0)]
                       [ks * 16 + ((lane & 16) ? 8 : 0)]);
                LDSM_X4(a[mt][ks][0], a[mt][ks][1], a[mt][ks][2], a[mt][ks][3], addr);
            }
#pragma unroll
        for (int nt = 0; nt < 8; ++nt) {
            uint32_t b[4];
            uint32_t addr = smem_u32(&Ws[wn * 64 + nt * 8 + (lane & 7)][(lane >> 3) * 8]);
            LDSM_X4(b[0], b[1], b[2], b[3], addr);
#pragma unroll
            for (int mt = 0; mt < 2; ++mt) {
                MMA_BF16(c[mt][nt][0], c[mt][nt][1], c[mt][nt][2], c[mt][nt][3],
                         a[mt][0][0], a[mt][0][1], a[mt][0][2], a[mt][0][3], b[0], b[1]);
                MMA_BF16(c[mt][nt][0], c[mt][nt][1], c[mt][nt][2], c[mt][nt][3],
                         a[mt][1][0], a[mt][1][1], a[mt][1][2], a[mt][1][3], b[2], b[3]);
            }
        }
    }

    float2 bj[8];
#pragma unroll
    for (int nt = 0; nt < 8; ++nt)
        bj[nt] = *(const float2*)(bias + colBase + wn * 64 + nt * 8 + tid4 * 2);

#pragma unroll
    for (int mt = 0; mt < 2; ++mt)
#pragma unroll
        for (int rh = 0; rh < 2; ++rh) {
            int grow = rowBase + wm * 32 + mt * 16 + groupID + rh * 8;
#pragma unroll
            for (int nt = 0; nt < 8; ++nt) {
                int j = colBase + wn * 64 + nt * 8 + tid4 * 2;
                size_t addr = (size_t)grow * CDIM + j;
                float2 sc = *(const float2*)(shortcut + addr);
                float2 ov;
                ov.x = c[mt][nt][rh * 2 + 0] + bj[nt].x + sc.x;
                ov.y = c[mt][nt][rh * 2 + 1] + bj[nt].y + sc.y;
                *(float2*)(Out + addr) = ov;
            }
        }
}

// ---------------------------------------------------------------------------
extern "C" void kernel_launch(void* const* d_in, const int* in_sizes, int n_in,
                              void* d_out, int out_size)
{
    const float* q  = (const float*)d_in[0];
    const float* k  = (const float*)d_in[1];
    const float* v  = (const float*)d_in[2];
    const float* Wq = (const float*)d_in[3];
    const float* bq = (const float*)d_in[4];
    const float* Wk = (const float*)d_in[5];
    const float* bk = (const float*)d_in[6];
    const float* Wv = (const float*)d_in[7];
    const float* bv = (const float*)d_in[8];
    const float* Wm = (const float*)d_in[9];
    const float* bm = (const float*)d_in[10];
    float* out = (float*)d_out;

    qkv_proj_kernel<<<dim3(M_ROWS / 128, CDIM / 128, 3), 256>>>(
        q, k, v, Wq, bq, Wk, bk, Wv, bv);
    attn_mma_kernel<<<dim3(8, BTH), 256>>>();
    final_bf16_kernel<<<dim3(M_ROWS / 128, CDIM / 128), 256>>>(Wm, bm, q, out);
}